// round 1
// baseline (speedup 1.0000x reference)
#include <cuda_runtime.h>

#define NN 40000
#define NE 640000

// Scratch (device globals are the sanctioned scratch mechanism — no runtime alloc)
__device__ __align__(128) float g_buf[NN * 128];
__device__ __align__(128) float h_buf[NN * 128];
__device__ int g_rowptr[NN + 1];

// ---------------------------------------------------------------------------
// Build CSR row pointers from SORTED dst array: row_ptr[n] = lower_bound(dst, n)
// ---------------------------------------------------------------------------
__global__ void build_rowptr(const int* __restrict__ dst) {
    int n = blockIdx.x * blockDim.x + threadIdx.x;
    if (n > NN) return;
    int lo = 0, hi = NE;
    while (lo < hi) {
        int mid = (lo + hi) >> 1;
        if (dst[mid] < n) lo = mid + 1; else hi = mid;
    }
    g_rowptr[n] = lo;
}

// ---------------------------------------------------------------------------
// GEMM: G[N,DOUT] = H[N,128] @ W[128,DOUT].  K=128 in a single staged pass.
// Block tile: 128 rows x DOUT cols, 256 threads, 8x(DOUT/16) microtile/thread.
// sHt is H-tile transposed [k][row] (pad 132 keeps float4 alignment).
// ---------------------------------------------------------------------------
template <int DOUT>
__global__ void __launch_bounds__(256)
gemm_nk128(const float* __restrict__ H, const float* __restrict__ W,
           float* __restrict__ G) {
    extern __shared__ float smem[];
    float* sHt = smem;                 // [128][132]
    float* sW  = smem + 128 * 132;     // [128][DOUT]

    const int tid = threadIdx.x;
    const int rowBase = blockIdx.x * 128;

    // Stage W (128 x DOUT) — coalesced float4
    for (int i = tid * 4; i < 128 * DOUT; i += 256 * 4) {
        *(float4*)&sW[i] = *(const float4*)&W[i];
    }

    // Stage H transposed: warp covers 8 rows x 4 k-quads (coalesced-ish loads,
    // ~2-way smem store conflicts)
    {
        int warpId = tid >> 5, lane = tid & 31;
        int rl = lane >> 2, ql = lane & 3;
        for (int w = warpId; w < 128; w += 8) {
            int rowBlock = w & 15, quadBlock = w >> 4;
            int row = rowBlock * 8 + rl;
            int kq  = quadBlock * 4 + ql;
            float4 v = make_float4(0.f, 0.f, 0.f, 0.f);
            int grow = rowBase + row;
            if (grow < NN) v = *(const float4*)&H[(size_t)grow * 128 + kq * 4];
            sHt[(kq * 4 + 0) * 132 + row] = v.x;
            sHt[(kq * 4 + 1) * 132 + row] = v.y;
            sHt[(kq * 4 + 2) * 132 + row] = v.z;
            sHt[(kq * 4 + 3) * 132 + row] = v.w;
        }
    }
    __syncthreads();

    constexpr int CPT = DOUT / 16;     // cols per thread: 8 (DOUT=128) or 4 (DOUT=64)
    const int tx = tid & 15, ty = tid >> 4;
    const int r0 = ty * 8, c0 = tx * CPT;

    float acc[8][CPT];
    #pragma unroll
    for (int i = 0; i < 8; i++)
        #pragma unroll
        for (int j = 0; j < CPT; j++) acc[i][j] = 0.f;

    #pragma unroll 4
    for (int k = 0; k < 128; k++) {
        float4 a0 = *(const float4*)(sHt + k * 132 + r0);
        float4 a1 = *(const float4*)(sHt + k * 132 + r0 + 4);
        float a[8] = {a0.x, a0.y, a0.z, a0.w, a1.x, a1.y, a1.z, a1.w};
        float b[CPT];
        #pragma unroll
        for (int jj = 0; jj < CPT; jj += 4) {
            float4 bv = *(const float4*)(sW + k * DOUT + c0 + jj);
            b[jj] = bv.x; b[jj + 1] = bv.y; b[jj + 2] = bv.z; b[jj + 3] = bv.w;
        }
        #pragma unroll
        for (int i = 0; i < 8; i++)
            #pragma unroll
            for (int j = 0; j < CPT; j++)
                acc[i][j] += a[i] * b[j];
    }

    // Writeback
    #pragma unroll
    for (int i = 0; i < 8; i++) {
        int grow = rowBase + r0 + i;
        if (grow < NN) {
            #pragma unroll
            for (int j = 0; j < CPT; j += 4) {
                float4 o = make_float4(acc[i][j], acc[i][j + 1],
                                       acc[i][j + 2], acc[i][j + 3]);
                *(float4*)&G[(size_t)grow * DOUT + c0 + j] = o;
            }
        }
    }
}

// ---------------------------------------------------------------------------
// Segment sum over sorted dst ranges: one warp per node, atomic-free.
// Out[n,:] = sum over edges e in [rowptr[n], rowptr[n+1]) of G[src[e],:]
// Lane covers DOUT/32 contiguous floats (float4 / float2 loads).
// ---------------------------------------------------------------------------
template <int DOUT>
__global__ void __launch_bounds__(256)
segsum_kernel(const float* __restrict__ G, const int* __restrict__ src,
              float* __restrict__ Out) {
    int gw = (blockIdx.x * 256 + threadIdx.x) >> 5;
    int lane = threadIdx.x & 31;
    if (gw >= NN) return;
    int s = g_rowptr[gw], e = g_rowptr[gw + 1];

    if constexpr (DOUT == 128) {
        float4 acc0 = make_float4(0, 0, 0, 0);
        float4 acc1 = make_float4(0, 0, 0, 0);
        for (int base = s; base < e; base += 32) {
            int cnt = min(32, e - base);
            int myidx = (base + lane < e) ? __ldg(&src[base + lane]) : 0;
            int j = 0;
            for (; j + 1 < cnt; j += 2) {
                int s0 = __shfl_sync(0xffffffffu, myidx, j);
                int s1 = __shfl_sync(0xffffffffu, myidx, j + 1);
                float4 x0 = __ldg((const float4*)(G + (size_t)s0 * 128) + lane);
                float4 x1 = __ldg((const float4*)(G + (size_t)s1 * 128) + lane);
                acc0.x += x0.x; acc0.y += x0.y; acc0.z += x0.z; acc0.w += x0.w;
                acc1.x += x1.x; acc1.y += x1.y; acc1.z += x1.z; acc1.w += x1.w;
            }
            if (j < cnt) {
                int s0 = __shfl_sync(0xffffffffu, myidx, j);
                float4 x0 = __ldg((const float4*)(G + (size_t)s0 * 128) + lane);
                acc0.x += x0.x; acc0.y += x0.y; acc0.z += x0.z; acc0.w += x0.w;
            }
        }
        float4 o = make_float4(acc0.x + acc1.x, acc0.y + acc1.y,
                               acc0.z + acc1.z, acc0.w + acc1.w);
        *((float4*)(Out + (size_t)gw * 128) + lane) = o;
    } else {  // DOUT == 64
        float2 acc0 = make_float2(0, 0);
        float2 acc1 = make_float2(0, 0);
        for (int base = s; base < e; base += 32) {
            int cnt = min(32, e - base);
            int myidx = (base + lane < e) ? __ldg(&src[base + lane]) : 0;
            int j = 0;
            for (; j + 1 < cnt; j += 2) {
                int s0 = __shfl_sync(0xffffffffu, myidx, j);
                int s1 = __shfl_sync(0xffffffffu, myidx, j + 1);
                float2 x0 = __ldg((const float2*)(G + (size_t)s0 * 64) + lane);
                float2 x1 = __ldg((const float2*)(G + (size_t)s1 * 64) + lane);
                acc0.x += x0.x; acc0.y += x0.y;
                acc1.x += x1.x; acc1.y += x1.y;
            }
            if (j < cnt) {
                int s0 = __shfl_sync(0xffffffffu, myidx, j);
                float2 x0 = __ldg((const float2*)(G + (size_t)s0 * 64) + lane);
                acc0.x += x0.x; acc0.y += x0.y;
            }
        }
        float2 o = make_float2(acc0.x + acc1.x, acc0.y + acc1.y);
        *((float2*)(Out + (size_t)gw * 64) + lane) = o;
    }
}

// ---------------------------------------------------------------------------
// Launch: rowptr once, then 3x (GEMM -> segment-sum).
// Layer algebra: segsum(h[src]) @ W == segsum((h @ W)[src])  (linearity),
// so GEMM-first halves layer-3 scatter traffic (64-wide rows).
// ---------------------------------------------------------------------------
extern "C" void kernel_launch(void* const* d_in, const int* in_sizes, int n_in,
                              void* d_out, int out_size) {
    const int*   src  = (const int*)d_in[0];
    const int*   dst  = (const int*)d_in[1];
    const float* feat = (const float*)d_in[2];
    const float* W1   = (const float*)d_in[3];
    const float* W2   = (const float*)d_in[4];
    const float* W3   = (const float*)d_in[5];
    float* out = (float*)d_out;

    float *gb, *hb;
    cudaGetSymbolAddress((void**)&gb, g_buf);
    cudaGetSymbolAddress((void**)&hb, h_buf);

    constexpr int SMEM128 = (128 * 132 + 128 * 128) * (int)sizeof(float);
    constexpr int SMEM64  = (128 * 132 + 128 * 64)  * (int)sizeof(float);
    cudaFuncSetAttribute(gemm_nk128<128>,
                         cudaFuncAttributeMaxDynamicSharedMemorySize, SMEM128);
    cudaFuncSetAttribute(gemm_nk128<64>,
                         cudaFuncAttributeMaxDynamicSharedMemorySize, SMEM64);

    const int GEMM_BLOCKS = (NN + 127) / 128;   // 313
    const int SEG_BLOCKS  = NN / 8;             // 5000 (8 warps/block, 1 warp/node)

    build_rowptr<<<(NN + 1 + 255) / 256, 256>>>(dst);

    // Layer 1
    gemm_nk128<128><<<GEMM_BLOCKS, 256, SMEM128>>>(feat, W1, gb);
    segsum_kernel<128><<<SEG_BLOCKS, 256>>>(gb, src, hb);
    // Layer 2
    gemm_nk128<128><<<GEMM_BLOCKS, 256, SMEM128>>>(hb, W2, gb);
    segsum_kernel<128><<<SEG_BLOCKS, 256>>>(gb, src, hb);
    // Layer 3
    gemm_nk128<64><<<GEMM_BLOCKS, 256, SMEM64>>>(hb, W3, gb);
    segsum_kernel<64><<<SEG_BLOCKS, 256>>>(gb, src, out);
}

// round 2
// speedup vs baseline: 1.1514x; 1.1514x over previous
#include <cuda_runtime.h>

#define NN 40000
#define NE 640000

// Scratch (device globals are the sanctioned scratch mechanism — no runtime alloc)
__device__ __align__(128) float g_buf[NN * 128];
__device__ __align__(128) float h_buf[NN * 128];
__device__ int g_rowptr[NN + 1];

typedef unsigned long long u64;

// Packed f32x2 FMA: d.lo += a.lo*b.lo ; d.hi += a.hi*b.hi
#define FMA_F32X2(d, a, b) \
    asm("fma.rn.f32x2 %0, %1, %2, %0;" : "+l"(d) : "l"(a), "l"(b))
// Duplicate a scalar float into both halves of a b64 reg
#define DUP_F32X2(d, f) \
    asm("mov.b64 %0, {%1, %1};" : "=l"(d) : "r"(__float_as_uint(f)))

// ---------------------------------------------------------------------------
// Build CSR row pointers from SORTED dst array: row_ptr[n] = lower_bound(dst, n)
// ---------------------------------------------------------------------------
__global__ void build_rowptr(const int* __restrict__ dst) {
    int n = blockIdx.x * blockDim.x + threadIdx.x;
    if (n > NN) return;
    int lo = 0, hi = NE;
    while (lo < hi) {
        int mid = (lo + hi) >> 1;
        if (dst[mid] < n) lo = mid + 1; else hi = mid;
    }
    g_rowptr[n] = lo;
}

// ---------------------------------------------------------------------------
// GEMM: G[N,DOUT] = H[N,128] @ W[128,DOUT] using packed fma.rn.f32x2.
//  - W staged in smem only (64KB / 32KB) -> 2 CTAs/SM, 16 warps/SM.
//  - A operand read straight from global: within a warp 16 lanes share the
//    same address (2 distinct addrs per LDG) -> broadcast, L1/L2 resident,
//    each H element is read by exactly one warp.
//  - Thread microtile: 8 rows x CPT cols, accumulated as CPT/2 f32x2 pairs.
// ---------------------------------------------------------------------------
template <int DOUT>
__global__ void __launch_bounds__(256, 2)
gemm_f32x2(const float* __restrict__ H, const float* __restrict__ W,
           float* __restrict__ G) {
    extern __shared__ float sW[];      // [128][DOUT]

    const int tid = threadIdx.x;
    // Stage W — coalesced float4
    #pragma unroll
    for (int i = tid * 4; i < 128 * DOUT; i += 256 * 4)
        *(float4*)&sW[i] = *(const float4*)&W[i];
    __syncthreads();

    constexpr int CPT = DOUT / 16;     // cols/thread: 8 (DOUT=128) or 4 (DOUT=64)
    constexpr int NP  = CPT / 2;       // f32x2 pairs: 4 or 2
    const int tx = tid & 15, ty = tid >> 4;
    const int rowBase = blockIdx.x * 128 + ty * 8;
    const int c0 = tx * CPT;

    // Clamped per-row base pointers (float2 granularity, k indexed by imm)
    const float2* hp[8];
    #pragma unroll
    for (int i = 0; i < 8; i++) {
        int r = rowBase + i;
        if (r >= NN) r = NN - 1;
        hp[i] = (const float2*)(H + (size_t)r * 128);
    }

    const u64* sWp = (const u64*)sW;   // pair view: row k has DOUT/2 pairs
    const int pbase = c0 >> 1;         // first pair index for this thread

    u64 acc[8][NP];
    #pragma unroll
    for (int i = 0; i < 8; i++)
        #pragma unroll
        for (int j = 0; j < NP; j++) acc[i][j] = 0ull;

    #pragma unroll 4
    for (int k2 = 0; k2 < 64; k2++) {          // two k per iteration
        float2 a[8];
        #pragma unroll
        for (int i = 0; i < 8; i++) a[i] = __ldg(&hp[i][k2]);

        u64 b0[NP], b1[NP];
        #pragma unroll
        for (int j = 0; j < NP; j += 2) {      // LDS.128: two pairs at a time
            ulonglong2 v0 = *(const ulonglong2*)&sWp[(2 * k2 + 0) * (DOUT / 2) + pbase + j];
            ulonglong2 v1 = *(const ulonglong2*)&sWp[(2 * k2 + 1) * (DOUT / 2) + pbase + j];
            b0[j] = v0.x; b0[j + 1] = v0.y;
            b1[j] = v1.x; b1[j + 1] = v1.y;
        }

        #pragma unroll
        for (int i = 0; i < 8; i++) {
            u64 a2;
            DUP_F32X2(a2, a[i].x);
            #pragma unroll
            for (int j = 0; j < NP; j++) FMA_F32X2(acc[i][j], a2, b0[j]);
        }
        #pragma unroll
        for (int i = 0; i < 8; i++) {
            u64 a2;
            DUP_F32X2(a2, a[i].y);
            #pragma unroll
            for (int j = 0; j < NP; j++) FMA_F32X2(acc[i][j], a2, b1[j]);
        }
    }

    // Writeback: pairs are (even,odd) consecutive cols -> direct 16B stores
    #pragma unroll
    for (int i = 0; i < 8; i++) {
        int grow = rowBase + i;
        if (grow < NN) {
            u64* dst = (u64*)(G + (size_t)grow * DOUT + c0);
            #pragma unroll
            for (int j = 0; j < NP; j += 2) {
                ulonglong2 o; o.x = acc[i][j]; o.y = acc[i][j + 1];
                *(ulonglong2*)(dst + j) = o;
            }
        }
    }
}

// ---------------------------------------------------------------------------
// Segment sum over sorted dst ranges: one warp per node, atomic-free.
// ---------------------------------------------------------------------------
template <int DOUT>
__global__ void __launch_bounds__(256)
segsum_kernel(const float* __restrict__ G, const int* __restrict__ src,
              float* __restrict__ Out) {
    int gw = (blockIdx.x * 256 + threadIdx.x) >> 5;
    int lane = threadIdx.x & 31;
    if (gw >= NN) return;
    int s = g_rowptr[gw], e = g_rowptr[gw + 1];

    if constexpr (DOUT == 128) {
        float4 acc0 = make_float4(0, 0, 0, 0);
        float4 acc1 = make_float4(0, 0, 0, 0);
        for (int base = s; base < e; base += 32) {
            int cnt = min(32, e - base);
            int myidx = (base + lane < e) ? __ldg(&src[base + lane]) : 0;
            int j = 0;
            for (; j + 1 < cnt; j += 2) {
                int s0 = __shfl_sync(0xffffffffu, myidx, j);
                int s1 = __shfl_sync(0xffffffffu, myidx, j + 1);
                float4 x0 = __ldg((const float4*)(G + (size_t)s0 * 128) + lane);
                float4 x1 = __ldg((const float4*)(G + (size_t)s1 * 128) + lane);
                acc0.x += x0.x; acc0.y += x0.y; acc0.z += x0.z; acc0.w += x0.w;
                acc1.x += x1.x; acc1.y += x1.y; acc1.z += x1.z; acc1.w += x1.w;
            }
            if (j < cnt) {
                int s0 = __shfl_sync(0xffffffffu, myidx, j);
                float4 x0 = __ldg((const float4*)(G + (size_t)s0 * 128) + lane);
                acc0.x += x0.x; acc0.y += x0.y; acc0.z += x0.z; acc0.w += x0.w;
            }
        }
        float4 o = make_float4(acc0.x + acc1.x, acc0.y + acc1.y,
                               acc0.z + acc1.z, acc0.w + acc1.w);
        *((float4*)(Out + (size_t)gw * 128) + lane) = o;
    } else {  // DOUT == 64
        float2 acc0 = make_float2(0, 0);
        float2 acc1 = make_float2(0, 0);
        for (int base = s; base < e; base += 32) {
            int cnt = min(32, e - base);
            int myidx = (base + lane < e) ? __ldg(&src[base + lane]) : 0;
            int j = 0;
            for (; j + 1 < cnt; j += 2) {
                int s0 = __shfl_sync(0xffffffffu, myidx, j);
                int s1 = __shfl_sync(0xffffffffu, myidx, j + 1);
                float2 x0 = __ldg((const float2*)(G + (size_t)s0 * 64) + lane);
                float2 x1 = __ldg((const float2*)(G + (size_t)s1 * 64) + lane);
                acc0.x += x0.x; acc0.y += x0.y;
                acc1.x += x1.x; acc1.y += x1.y;
            }
            if (j < cnt) {
                int s0 = __shfl_sync(0xffffffffu, myidx, j);
                float2 x0 = __ldg((const float2*)(G + (size_t)s0 * 64) + lane);
                acc0.x += x0.x; acc0.y += x0.y;
            }
        }
        float2 o = make_float2(acc0.x + acc1.x, acc0.y + acc1.y);
        *((float2*)(Out + (size_t)gw * 64) + lane) = o;
    }
}

// ---------------------------------------------------------------------------
// Launch: rowptr once, then 3x (GEMM -> segment-sum).
// segsum(h[src]) @ W == segsum((h @ W)[src])  -> GEMM-first halves layer-3
// scatter width.
// ---------------------------------------------------------------------------
extern "C" void kernel_launch(void* const* d_in, const int* in_sizes, int n_in,
                              void* d_out, int out_size) {
    const int*   src  = (const int*)d_in[0];
    const int*   dst  = (const int*)d_in[1];
    const float* feat = (const float*)d_in[2];
    const float* W1   = (const float*)d_in[3];
    const float* W2   = (const float*)d_in[4];
    const float* W3   = (const float*)d_in[5];
    float* out = (float*)d_out;

    float *gb, *hb;
    cudaGetSymbolAddress((void**)&gb, g_buf);
    cudaGetSymbolAddress((void**)&hb, h_buf);

    constexpr int SMEM128 = 128 * 128 * (int)sizeof(float);  // 64 KB
    constexpr int SMEM64  = 128 * 64  * (int)sizeof(float);  // 32 KB
    cudaFuncSetAttribute(gemm_f32x2<128>,
                         cudaFuncAttributeMaxDynamicSharedMemorySize, SMEM128);
    cudaFuncSetAttribute(gemm_f32x2<64>,
                         cudaFuncAttributeMaxDynamicSharedMemorySize, SMEM64);

    const int GEMM_BLOCKS = (NN + 127) / 128;   // 313
    const int SEG_BLOCKS  = NN / 8;             // 5000 (8 warps/block, 1 warp/node)

    build_rowptr<<<(NN + 1 + 255) / 256, 256>>>(dst);

    // Layer 1
    gemm_f32x2<128><<<GEMM_BLOCKS, 256, SMEM128>>>(feat, W1, gb);
    segsum_kernel<128><<<SEG_BLOCKS, 256>>>(gb, src, hb);
    // Layer 2
    gemm_f32x2<128><<<GEMM_BLOCKS, 256, SMEM128>>>(hb, W2, gb);
    segsum_kernel<128><<<SEG_BLOCKS, 256>>>(gb, src, hb);
    // Layer 3
    gemm_f32x2<64><<<GEMM_BLOCKS, 256, SMEM64>>>(hb, W3, gb);
    segsum_kernel<64><<<SEG_BLOCKS, 256>>>(gb, src, out);
}

// round 4
// speedup vs baseline: 2.2358x; 1.9419x over previous
#include <cuda_runtime.h>
#include <cstdint>

#define NN 40000
#define NE 640000

// ---- device scratch (static globals: the sanctioned scratch mechanism) ----
__device__ __align__(128) float g_buf[NN * 64];
__device__ __align__(128) float h_buf[NN * 64];
__device__ __align__(128) float w12_buf[128 * 128];
__device__ __align__(128) float w123_buf[128 * 64];
__device__ int g_rowptr[NN + 1];

typedef unsigned long long u64;

// Packed f32x2 FMA: d.lo += a.lo*b.lo ; d.hi += a.hi*b.hi
#define FMA_F32X2(d, a, b) \
    asm("fma.rn.f32x2 %0, %1, %2, %0;" : "+l"(d) : "l"(a), "l"(b))
#define DUP_F32X2(d, f) \
    asm("mov.b64 %0, {%1, %1};" : "=l"(d) : "r"(__float_as_uint(f)))

// ---------------------------------------------------------------------------
// CSR row pointers from SORTED dst: row_ptr[n] = lower_bound(dst, n)
// ---------------------------------------------------------------------------
__global__ void build_rowptr(const int* __restrict__ dst) {
    int n = blockIdx.x * blockDim.x + threadIdx.x;
    if (n > NN) return;
    int lo = 0, hi = NE;
    while (lo < hi) {
        int mid = (lo + hi) >> 1;
        if (dst[mid] < n) lo = mid + 1; else hi = mid;
    }
    g_rowptr[n] = lo;
}

// ---------------------------------------------------------------------------
// Small dense matmul C[M,N] = A[M,K] @ B[K,N], one thread per output element.
// Used for W12 = W1@W2 (128x128) and W123 = W12@W3 (128x64). Tiny.
// ---------------------------------------------------------------------------
__global__ void matmul_small(const float* __restrict__ A,
                             const float* __restrict__ B,
                             float* __restrict__ C, int K, int Ncols, int total) {
    int idx = blockIdx.x * blockDim.x + threadIdx.x;
    if (idx >= total) return;
    int i = idx / Ncols, j = idx % Ncols;
    float acc = 0.f;
    #pragma unroll 8
    for (int k = 0; k < K; k++)
        acc += __ldg(&A[i * K + k]) * __ldg(&B[k * Ncols + j]);
    C[idx] = acc;
}

// ---------------------------------------------------------------------------
// GEMM: X[N,64] = F[N,128] @ W[128,64] using packed fma.rn.f32x2.
//  - W staged in smem (32KB), A read straight from global (lane-broadcast).
//  - Thread microtile 8 rows x 4 cols (2 f32x2 pairs).
// ---------------------------------------------------------------------------
__global__ void __launch_bounds__(256, 2)
gemm_f32x2_64(const float* __restrict__ H, const float* __restrict__ W,
              float* __restrict__ G) {
    __shared__ float sW[128 * 64];

    const int tid = threadIdx.x;
    #pragma unroll
    for (int i = tid * 4; i < 128 * 64; i += 256 * 4)
        *(float4*)&sW[i] = *(const float4*)&W[i];
    __syncthreads();

    constexpr int CPT = 4, NP = 2;
    const int tx = tid & 15, ty = tid >> 4;
    const int rowBase = blockIdx.x * 128 + ty * 8;
    const int c0 = tx * CPT;

    const float2* hp[8];
    #pragma unroll
    for (int i = 0; i < 8; i++) {
        int r = rowBase + i;
        if (r >= NN) r = NN - 1;
        hp[i] = (const float2*)(H + (size_t)r * 128);
    }

    const u64* sWp = (const u64*)sW;   // row k has 32 pairs
    const int pbase = c0 >> 1;

    u64 acc[8][NP];
    #pragma unroll
    for (int i = 0; i < 8; i++)
        #pragma unroll
        for (int j = 0; j < NP; j++) acc[i][j] = 0ull;

    #pragma unroll 4
    for (int k2 = 0; k2 < 64; k2++) {          // two k per iteration
        float2 a[8];
        #pragma unroll
        for (int i = 0; i < 8; i++) a[i] = __ldg(&hp[i][k2]);

        ulonglong2 v0 = *(const ulonglong2*)&sWp[(2 * k2 + 0) * 32 + pbase];
        ulonglong2 v1 = *(const ulonglong2*)&sWp[(2 * k2 + 1) * 32 + pbase];

        #pragma unroll
        for (int i = 0; i < 8; i++) {
            u64 a2;
            DUP_F32X2(a2, a[i].x);
            FMA_F32X2(acc[i][0], a2, v0.x);
            FMA_F32X2(acc[i][1], a2, v0.y);
        }
        #pragma unroll
        for (int i = 0; i < 8; i++) {
            u64 a2;
            DUP_F32X2(a2, a[i].y);
            FMA_F32X2(acc[i][0], a2, v1.x);
            FMA_F32X2(acc[i][1], a2, v1.y);
        }
    }

    #pragma unroll
    for (int i = 0; i < 8; i++) {
        int grow = rowBase + i;
        if (grow < NN) {
            ulonglong2 o; o.x = acc[i][0]; o.y = acc[i][1];
            *(ulonglong2*)(G + (size_t)grow * 64 + c0) = o;
        }
    }
}

// ---------------------------------------------------------------------------
// Segment sum (width 64, fp32): one warp per node, atomic-free, sorted dst.
// ---------------------------------------------------------------------------
__global__ void __launch_bounds__(256)
segsum64(const float* __restrict__ G, const int* __restrict__ src,
         float* __restrict__ Out) {
    int gw = (blockIdx.x * 256 + threadIdx.x) >> 5;
    int lane = threadIdx.x & 31;
    if (gw >= NN) return;
    int s = g_rowptr[gw], e = g_rowptr[gw + 1];

    float2 acc0 = make_float2(0, 0);
    float2 acc1 = make_float2(0, 0);
    for (int base = s; base < e; base += 32) {
        int cnt = min(32, e - base);
        int myidx = (base + lane < e) ? __ldg(&src[base + lane]) : 0;
        int j = 0;
        for (; j + 1 < cnt; j += 2) {
            int s0 = __shfl_sync(0xffffffffu, myidx, j);
            int s1 = __shfl_sync(0xffffffffu, myidx, j + 1);
            float2 x0 = __ldg((const float2*)(G + (size_t)s0 * 64) + lane);
            float2 x1 = __ldg((const float2*)(G + (size_t)s1 * 64) + lane);
            acc0.x += x0.x; acc0.y += x0.y;
            acc1.x += x1.x; acc1.y += x1.y;
        }
        if (j < cnt) {
            int s0 = __shfl_sync(0xffffffffu, myidx, j);
            float2 x0 = __ldg((const float2*)(G + (size_t)s0 * 64) + lane);
            acc0.x += x0.x; acc0.y += x0.y;
        }
    }
    float2 o = make_float2(acc0.x + acc1.x, acc0.y + acc1.y);
    *((float2*)(Out + (size_t)gw * 64) + lane) = o;
}

// ---------------------------------------------------------------------------
// Launch.  Algebra: segment_sum is a linear operator S on the node axis and
// commutes with right-multiplication by W, so
//   S(S(S F W1) W2) W3  ==  S^3 (F (W1 W2 W3))
// -> one 128->64 GEMM + three width-64 segment sums.
// ---------------------------------------------------------------------------
extern "C" void kernel_launch(void* const* d_in, const int* in_sizes, int n_in,
                              void* d_out, int out_size) {
    const int*   src  = (const int*)d_in[0];
    const int*   dst  = (const int*)d_in[1];
    const float* feat = (const float*)d_in[2];
    const float* W1   = (const float*)d_in[3];
    const float* W2   = (const float*)d_in[4];
    const float* W3   = (const float*)d_in[5];
    float* out = (float*)d_out;

    float *gb, *hb, *w12, *w123;
    cudaGetSymbolAddress((void**)&gb,   g_buf);
    cudaGetSymbolAddress((void**)&hb,   h_buf);
    cudaGetSymbolAddress((void**)&w12,  w12_buf);
    cudaGetSymbolAddress((void**)&w123, w123_buf);

    const int GEMM_BLOCKS = (NN + 127) / 128;  // 313
    const int SEG_BLOCKS  = NN / 8;            // 5000

    build_rowptr<<<(NN + 1 + 255) / 256, 256>>>(dst);

    // W123 = W1 @ W2 @ W3  (tiny)
    matmul_small<<<(128 * 128 + 255) / 256, 256>>>(W1, W2, w12, 128, 128, 128 * 128);
    matmul_small<<<(128 * 64 + 255) / 256, 256>>>(w12, W3, w123, 128, 64, 128 * 64);

    // X = F @ W123
    gemm_f32x2_64<<<GEMM_BLOCKS, 256>>>(feat, w123, gb);

    // out = S^3 X
    segsum64<<<SEG_BLOCKS, 256>>>(gb, src, hb);
    segsum64<<<SEG_BLOCKS, 256>>>(hb, src, gb);
    segsum64<<<SEG_BLOCKS, 256>>>(gb, src, out);
}